// round 15
// baseline (speedup 1.0000x reference)
#include <cuda_runtime.h>
#include <cuda_bf16.h>
#include <cuda_fp16.h>
#include <math.h>

#define BB 8
#define CC 256
#define NN 2304   // 48*48
#define NT (NN/32)

typedef unsigned long long u64;
typedef unsigned int u32;

__device__ __forceinline__ u32 s2u(const void* p) {
    return (u32)__cvta_generic_to_shared(p);
}
__device__ __forceinline__ void ldsm4(u32* r, u32 a) {
    asm volatile("ldmatrix.sync.aligned.m8n8.x4.shared.b16 {%0,%1,%2,%3},[%4];"
        : "=r"(r[0]), "=r"(r[1]), "=r"(r[2]), "=r"(r[3]) : "r"(a));
}
__device__ __forceinline__ void ldsm4t(u32* r, u32 a) {
    asm volatile("ldmatrix.sync.aligned.m8n8.x4.trans.shared.b16 {%0,%1,%2,%3},[%4];"
        : "=r"(r[0]), "=r"(r[1]), "=r"(r[2]), "=r"(r[3]) : "r"(a));
}
__device__ __forceinline__ void mma_bf16(float* c, const u32* a, u32 b0, u32 b1) {
    asm volatile("mma.sync.aligned.m16n8k16.row.col.f32.bf16.bf16.f32 "
        "{%0,%1,%2,%3},{%4,%5,%6,%7},{%8,%9},{%0,%1,%2,%3};"
        : "+f"(c[0]), "+f"(c[1]), "+f"(c[2]), "+f"(c[3])
        : "r"(a[0]), "r"(a[1]), "r"(a[2]), "r"(a[3]), "r"(b0), "r"(b1));
}
__device__ __forceinline__ void mma_f16(float* c, const u32* a, u32 b0, u32 b1) {
    asm volatile("mma.sync.aligned.m16n8k16.row.col.f32.f16.f16.f32 "
        "{%0,%1,%2,%3},{%4,%5,%6,%7},{%8,%9},{%0,%1,%2,%3};"
        : "+f"(c[0]), "+f"(c[1]), "+f"(c[2]), "+f"(c[3])
        : "r"(a[0]), "r"(a[1]), "r"(a[2]), "r"(a[3]), "r"(b0), "r"(b1));
}
// packs {lo -> bits[15:0], hi -> bits[31:16]}
__device__ __forceinline__ u32 cvt_bf16x2(float hi, float lo) {
    u32 r; asm("cvt.rn.bf16x2.f32 %0,%1,%2;" : "=r"(r) : "f"(hi), "f"(lo)); return r;
}
__device__ __forceinline__ u32 cvt_f16x2(float hi, float lo) {
    u32 r; asm("cvt.rn.f16x2.f32 %0,%1,%2;" : "=r"(r) : "f"(hi), "f"(lo)); return r;
}
__device__ __forceinline__ void cpasync16(u32 dst, const void* src) {
    asm volatile("cp.async.cg.shared.global [%0],[%1],16;" :: "r"(dst), "l"(src));
}
__device__ __forceinline__ void cpcommit() { asm volatile("cp.async.commit_group;"); }
__device__ __forceinline__ void cpwait0()  { asm volatile("cp.async.wait_group 0;"); }

// Scratch (cudaMalloc banned -> __device__ globals).
// Q/K: fp16 (fp16 products exact in fp32 accum; logit err ~4e-3, safe).
// V:   bf16 (P reaches e^28 -> P must be bf16; V matches).
// branch 0: Q/K from y-projections (attn2), V = v1 (from x)  -> out1
// branch 1: Q/K from x-projections (attn1), V = v2 (from y)  -> out2
__device__ __half        g_qf[2][BB][NN][32];
__device__ __half        g_kf[2][BB][NN][32];
__device__ __nv_bfloat16 g_vb[2][BB][NN][CC];

// split fp32 -> bf16 hi/lo, pack 8 values into 16B stores
__device__ __forceinline__ void split_store8(const float* v,
                                             __nv_bfloat16* hd, __nv_bfloat16* ld) {
    u32 hw[4], lw[4];
    #pragma unroll
    for (int i = 0; i < 4; i++) {
        float a = v[2*i], b = v[2*i+1];
        __nv_bfloat16 ha = __float2bfloat16(a), hb = __float2bfloat16(b);
        hw[i] = cvt_bf16x2(__bfloat162float(hb), __bfloat162float(ha));
        lw[i] = cvt_bf16x2(b - __bfloat162float(hb), a - __bfloat162float(ha));
    }
    *(uint4*)hd = make_uint4(hw[0], hw[1], hw[2], hw[3]);
    *(uint4*)ld = make_uint4(lw[0], lw[1], lw[2], lw[3]);
}
// fp32 -> fp16, pack 8 values into one 16B store
__device__ __forceinline__ void f16_store8(const float* v, void* d) {
    u32 hw[4];
    #pragma unroll
    for (int i = 0; i < 4; i++)
        hw[i] = cvt_f16x2(v[2*i+1], v[2*i]);
    *(uint4*)d = make_uint4(hw[0], hw[1], hw[2], hw[3]);
}

// ---------------------------------------------------------------------------
// Tensor-core projection GEMM: out[o][n] = sum_c W[o][c] * X[c][n] + bias[o]
// Q/K blocks (O0==0): split-bf16, 3 mma passes (fp32-level; feeds exp()).
// V blocks (O0>=64):  single-pass fp16 (error ~1e-3, hidden under bf16 store).
// (unchanged from R14)
// ---------------------------------------------------------------------------
__global__ __launch_bounds__(256) void proj_tc_kernel(
    const float* __restrict__ x, const float* __restrict__ y,
    const float* __restrict__ wqx, const float* __restrict__ bqx,
    const float* __restrict__ wkx, const float* __restrict__ bkx,
    const float* __restrict__ wvx, const float* __restrict__ bvx,
    const float* __restrict__ wqy, const float* __restrict__ bqy,
    const float* __restrict__ wky, const float* __restrict__ bky,
    const float* __restrict__ wvy, const float* __restrict__ bvy)
{
    const int inp = blockIdx.z >> 3;
    const int b   = blockIdx.z & 7;
    const int n0  = blockIdx.x * 64;
    const int O0  = blockIdx.y * 64;
    const bool isQK = (O0 == 0);

    const float* in = inp ? y : x;
    const float* wq = inp ? wqy : wqx;  const float* bq = inp ? bqy : bqx;
    const float* wk = inp ? wky : wkx;  const float* bk = inp ? bky : bkx;
    const float* wv = inp ? wvy : wvx;  const float* bv = inp ? bvy : bvx;
    const int qb = inp ? 0 : 1;
    const int vb = inp ? 1 : 0;

    __shared__ __align__(16) char smemraw[19968];
    __nv_bfloat16* sWh = (__nv_bfloat16*)smemraw;          // qk: bf16-hi | v: fp16
    __nv_bfloat16* sWl = sWh + 64 * 40;
    __nv_bfloat16* sXh = sWl + 64 * 40;                    // qk: bf16-hi | v: fp16
    __nv_bfloat16* sXl = sXh + 32 * 72;
    float* sT = (float*)smemraw;          // [64][68]

    const int tid = threadIdx.x;
    const int w = tid >> 5, l = tid & 31;
    const int rg = w & 3, ng = w >> 2;
    const int grp = l >> 2, t4 = l & 3;
    const int lrow = l & 15;
    const int hi8 = (l & 16) ? 8 : 0;

    const int wrow_i = tid >> 2;
    const int wcseg  = (tid & 3) * 8;
    const int og = O0 + wrow_i;
    const float* wrow = (og < 32) ? (wq + (size_t)og * CC)
                      : (og < 64) ? (wk + (size_t)(og - 32) * CC)
                                  : (wv + (size_t)(og - 64) * CC);
    const int xrow_i = tid >> 3;
    const int xnseg  = (tid & 7) * 8;
    const float* xbase = in + ((size_t)b * CC + xrow_i) * NN + n0 + xnseg;

    float acc[4][4];
    #pragma unroll
    for (int t = 0; t < 4; t++)
        #pragma unroll
        for (int i = 0; i < 4; i++) acc[t][i] = 0.f;

    for (int c0 = 0; c0 < CC; c0 += 32) {
        {
            float4 wa = *(const float4*)(wrow + c0 + wcseg);
            float4 wb = *(const float4*)(wrow + c0 + wcseg + 4);
            float v[8] = {wa.x, wa.y, wa.z, wa.w, wb.x, wb.y, wb.z, wb.w};
            if (isQK) split_store8(v, &sWh[wrow_i * 40 + wcseg], &sWl[wrow_i * 40 + wcseg]);
            else      f16_store8(v, &sWh[wrow_i * 40 + wcseg]);
        }
        {
            const float* xp = xbase + (size_t)c0 * NN;
            float4 xa = *(const float4*)xp;
            float4 xc = *(const float4*)(xp + 4);
            float v[8] = {xa.x, xa.y, xa.z, xa.w, xc.x, xc.y, xc.z, xc.w};
            if (isQK) split_store8(v, &sXh[xrow_i * 72 + xnseg], &sXl[xrow_i * 72 + xnseg]);
            else      f16_store8(v, &sXh[xrow_i * 72 + xnseg]);
        }
        __syncthreads();

        if (isQK) {
            #pragma unroll
            for (int kc = 0; kc < 2; kc++) {
                u32 ah[4], al[4];
                ldsm4(ah, s2u(&sWh[(rg * 16 + lrow) * 40 + kc * 16 + hi8]));
                ldsm4(al, s2u(&sWl[(rg * 16 + lrow) * 40 + kc * 16 + hi8]));
                #pragma unroll
                for (int sp = 0; sp < 2; sp++) {
                    u32 bh[4], bl[4];
                    int xoff = (kc * 16 + lrow) * 72 + ng * 32 + sp * 16 + hi8;
                    ldsm4t(bh, s2u(&sXh[xoff]));
                    ldsm4t(bl, s2u(&sXl[xoff]));
                    int t = sp * 2;
                    mma_bf16(acc[t], ah, bh[0], bh[1]);
                    mma_bf16(acc[t], ah, bl[0], bl[1]);
                    mma_bf16(acc[t], al, bh[0], bh[1]);
                    mma_bf16(acc[t+1], ah, bh[2], bh[3]);
                    mma_bf16(acc[t+1], ah, bl[2], bl[3]);
                    mma_bf16(acc[t+1], al, bh[2], bh[3]);
                }
            }
        } else {
            #pragma unroll
            for (int kc = 0; kc < 2; kc++) {
                u32 ah[4];
                ldsm4(ah, s2u(&sWh[(rg * 16 + lrow) * 40 + kc * 16 + hi8]));
                #pragma unroll
                for (int sp = 0; sp < 2; sp++) {
                    u32 bh[4];
                    int xoff = (kc * 16 + lrow) * 72 + ng * 32 + sp * 16 + hi8;
                    ldsm4t(bh, s2u(&sXh[xoff]));
                    int t = sp * 2;
                    mma_f16(acc[t],   ah, bh[0], bh[1]);
                    mma_f16(acc[t+1], ah, bh[2], bh[3]);
                }
            }
        }
        __syncthreads();
    }

    const int ol0 = rg * 16 + grp, ol1 = ol0 + 8;
    float bias0, bias1;
    {
        int o0g = O0 + ol0, o1g = O0 + ol1;
        bias0 = (o0g < 32) ? bq[o0g] : (o0g < 64) ? bk[o0g - 32] : bv[o0g - 64];
        bias1 = (o1g < 32) ? bq[o1g] : (o1g < 64) ? bk[o1g - 32] : bv[o1g - 64];
    }

    // transpose via smem: sT[n_local][o_local]
    #pragma unroll
    for (int t = 0; t < 4; t++) {
        int nl = ng * 32 + (t >> 1) * 16 + (t & 1) * 8 + 2 * t4;
        sT[nl * 68 + ol0]       = acc[t][0] + bias0;
        sT[(nl + 1) * 68 + ol0] = acc[t][1] + bias0;
        sT[nl * 68 + ol1]       = acc[t][2] + bias1;
        sT[(nl + 1) * 68 + ol1] = acc[t][3] + bias1;
    }
    __syncthreads();

    {
        int row  = tid >> 2;
        int oseg = (tid & 3) * 16;
        int n = n0 + row;
        float4 v0 = *(const float4*)&sT[row * 68 + oseg];
        float4 v1 = *(const float4*)&sT[row * 68 + oseg + 4];
        float4 v2 = *(const float4*)&sT[row * 68 + oseg + 8];
        float4 v3 = *(const float4*)&sT[row * 68 + oseg + 12];
        float vv[16] = {v0.x,v0.y,v0.z,v0.w, v1.x,v1.y,v1.z,v1.w,
                        v2.x,v2.y,v2.z,v2.w, v3.x,v3.y,v3.z,v3.w};
        if (isQK) {
            // q/k path: fp16
            u32 hw[8];
            #pragma unroll
            for (int i = 0; i < 8; i++)
                hw[i] = cvt_f16x2(vv[2*i+1], vv[2*i]);
            if (oseg < 32) {
                *(uint4*)&g_qf[qb][b][n][oseg]     = make_uint4(hw[0],hw[1],hw[2],hw[3]);
                *(uint4*)&g_qf[qb][b][n][oseg + 8] = make_uint4(hw[4],hw[5],hw[6],hw[7]);
            } else {
                int ko = oseg - 32;
                *(uint4*)&g_kf[qb][b][n][ko]     = make_uint4(hw[0],hw[1],hw[2],hw[3]);
                *(uint4*)&g_kf[qb][b][n][ko + 8] = make_uint4(hw[4],hw[5],hw[6],hw[7]);
            }
        } else {
            int cb = O0 - 64 + oseg;
            u32 hw[8];
            #pragma unroll
            for (int i = 0; i < 8; i++)
                hw[i] = cvt_bf16x2(vv[2*i+1], vv[2*i]);
            *(uint4*)&g_vb[vb][b][n][cb]     = make_uint4(hw[0],hw[1],hw[2],hw[3]);
            *(uint4*)&g_vb[vb][b][n][cb + 8] = make_uint4(hw[4],hw[5],hw[6],hw[7]);
        }
    }
}

// ---------------------------------------------------------------------------
// Tensor-core fused attention: same-tile PV, fp16 single-pass S, bf16 P/V,
// no-max softmax. NEW in this round: ONE barrier per tile. Prefetch for
// tile t+1 is issued AFTER sync(t), so the buffer it overwrites (read at
// tile t-1) is provably quiescent — trailing barrier removed.
// smem: sQ[64][40] fp16 (5120B) | sK 2x[32][40] fp16 (5120B)
//       | sV 2x[32][264] bf16 (33792B)  => 44032B
// ---------------------------------------------------------------------------
#define ATTN_SMEM 44032

__global__ __launch_bounds__(256, 2) void attn_kernel(
    const float* __restrict__ x, const float* __restrict__ y,
    const float* __restrict__ gx, const float* __restrict__ gy,
    float* __restrict__ out)
{
    const int br  = blockIdx.z;
    const int b   = blockIdx.y;
    const int i0  = blockIdx.x * 64;
    const int tid = threadIdx.x;
    const int w   = tid >> 5;
    const int l   = tid & 31;
    const int rg  = w & 3;
    const int ch  = w >> 2;
    const int grp = l >> 2;
    const int t4  = l & 3;
    const int q0  = rg * 16;

    const float* res = br ? y : x;
    const float* gmm = br ? gy : gx;
    float* outp = out + (size_t)br * BB * CC * NN;

    extern __shared__ __align__(16) char sm[];
    __half*        sQ = (__half*)sm;                   // [64][40]
    __half*        sK = (__half*)(sm + 5120);          // 2 x [32][40]
    __nv_bfloat16* sV = (__nv_bfloat16*)(sm + 10240);  // 2 x [32][264]

    // Stage Q: 64 rows x 32 fp16
    {
        int row = tid >> 2, c8 = (tid & 3) * 8;
        *(float4*)&sQ[row * 40 + c8] = *(const float4*)&g_qf[br][b][i0 + row][c8];
    }
    __syncthreads();

    // Persistent Q fragments: rows q0..q0+15, k chunks 0/1
    u32 qf[2][4];
    {
        int row = q0 + (l & 15);
        int cofs = (l & 16) ? 8 : 0;
        #pragma unroll
        for (int kc = 0; kc < 2; kc++)
            ldsm4(qf[kc], s2u(&sQ[row * 40 + kc * 16 + cofs]));
    }

    const __half*        kg = &g_kf[br][b][0][0];
    const __nv_bfloat16* vg = &g_vb[br][b][0][0];

    const int krow = tid >> 2;          // tid<128: K rows 0..31
    const int kc8  = (tid & 3) * 8;

    float acc[16][4];
    #pragma unroll
    for (int t = 0; t < 16; t++)
        #pragma unroll
        for (int i = 0; i < 4; i++) acc[t][i] = 0.f;
    float lsA = 0.f, lsB = 0.f;

    // prologue: loads for tile 0 into buf 0
    {
        if (tid < 128)
            cpasync16(s2u(&sK[krow * 40 + kc8]), kg + (size_t)krow * 32 + kc8);
        #pragma unroll
        for (int it = 0; it < 4; it++) {
            int idx = tid + it * 256;
            int vr = idx >> 5, vc8 = (idx & 31) * 8;
            cpasync16(s2u(&sV[vr * 264 + vc8]), vg + (size_t)vr * CC + vc8);
        }
        cpcommit();
    }

    const int ldA = (l & 16) ? 8 : 0;
    const int krA = ((l >> 4) << 3) + (l & 7);
    const int kcA = ((l >> 3) & 1) * 8;

    for (int t = 0; t < NT; t++) {
        const int buf = t & 1;

        // Data for tile t was issued last iteration (or prologue): wait + sync.
        cpwait0();
        __syncthreads();

        // Issue prefetch for tile t+1 into the other buffer. Safe: that
        // buffer's readers (tile t-1) all passed the sync above.
        if (t + 1 < NT) {
            const int nb = buf ^ 1;
            const int j1 = (t + 1) * 32;
            if (tid < 128)
                cpasync16(s2u(&sK[nb * 1280 + krow * 40 + kc8]),
                          kg + (size_t)(j1 + krow) * 32 + kc8);
            #pragma unroll
            for (int it = 0; it < 4; it++) {
                int idx = tid + it * 256;
                int vr = idx >> 5, vc8 = (idx & 31) * 8;
                cpasync16(s2u(&sV[nb * 8448 + vr * 264 + vc8]),
                          vg + (size_t)(j1 + vr) * CC + vc8);
            }
            cpcommit();
        }

        const __half*        bK = sK + buf * 1280;
        const __nv_bfloat16* bV = sV + buf * 8448;

        // S phase (single-pass fp16): 4 n8 j-tiles for this warp's 16 rows
        float sc[4][4];
        #pragma unroll
        for (int tt = 0; tt < 4; tt++)
            #pragma unroll
            for (int i = 0; i < 4; i++) sc[tt][i] = 0.f;

        #pragma unroll
        for (int jg = 0; jg < 2; jg++) {
            #pragma unroll
            for (int kc = 0; kc < 2; kc++) {
                u32 k4[4];
                ldsm4(k4, s2u(&bK[(jg * 16 + krA) * 40 + kc * 16 + kcA]));
                mma_f16(sc[jg * 2],     qf[kc], k4[0], k4[1]);
                mma_f16(sc[jg * 2 + 1], qf[kc], k4[2], k4[3]);
            }
        }

        // exp + pack P A-frags in registers
        u32 pa[2][4];
        #pragma unroll
        for (int tt = 0; tt < 4; tt++) {
            float e0 = __expf(sc[tt][0]);
            float e1 = __expf(sc[tt][1]);
            float e2 = __expf(sc[tt][2]);
            float e3 = __expf(sc[tt][3]);
            lsA += e0 + e1;
            lsB += e2 + e3;
            int kj = tt >> 1, sub = (tt & 1) * 2;
            pa[kj][sub]     = cvt_bf16x2(e1, e0);
            pa[kj][sub + 1] = cvt_bf16x2(e3, e2);
        }

        // PV: B = V frags via ldsm4t (same tile)
        #pragma unroll
        for (int g = 0; g < 8; g++) {
            int n0 = ch * 128 + g * 16 + ldA;
            #pragma unroll
            for (int kj = 0; kj < 2; kj++) {
                u32 vb4[4];
                ldsm4t(vb4, s2u(&bV[(kj * 16 + (l & 15)) * 264 + n0]));
                mma_bf16(acc[g * 2],     pa[kj], vb4[0], vb4[1]);
                mma_bf16(acc[g * 2 + 1], pa[kj], vb4[2], vb4[3]);
            }
        }
    }

    // lsum: quad reduce (lanes in a quad hold disjoint j columns)
    lsA += __shfl_xor_sync(0xffffffffu, lsA, 1);
    lsA += __shfl_xor_sync(0xffffffffu, lsA, 2);
    lsB += __shfl_xor_sync(0xffffffffu, lsB, 1);
    lsB += __shfl_xor_sync(0xffffffffu, lsB, 2);

    const float g = gmm[0];
    float rl0 = g / lsA, rl1 = g / lsB;
    int ir0 = i0 + q0 + grp;
    int ir1 = ir0 + 8;
    #pragma unroll
    for (int t = 0; t < 16; t++) {
        int c0 = ch * 128 + t * 8 + 2 * t4;
        size_t base = ((size_t)b * CC + c0) * NN;
        outp[base + ir0]      = acc[t][0] * rl0 + res[base + ir0];
        outp[base + NN + ir0] = acc[t][1] * rl0 + res[base + NN + ir0];
        outp[base + ir1]      = acc[t][2] * rl1 + res[base + ir1];
        outp[base + NN + ir1] = acc[t][3] * rl1 + res[base + NN + ir1];
    }
}

// ---------------------------------------------------------------------------

extern "C" void kernel_launch(void* const* d_in, const int* in_sizes, int n_in,
                              void* d_out, int out_size)
{
    const float* x   = (const float*)d_in[0];
    const float* y   = (const float*)d_in[1];
    const float* wqx = (const float*)d_in[2];
    const float* bqx = (const float*)d_in[3];
    const float* wkx = (const float*)d_in[4];
    const float* bkx = (const float*)d_in[5];
    const float* wvx = (const float*)d_in[6];
    const float* bvx = (const float*)d_in[7];
    const float* wqy = (const float*)d_in[8];
    const float* bqy = (const float*)d_in[9];
    const float* wky = (const float*)d_in[10];
    const float* bky = (const float*)d_in[11];
    const float* wvy = (const float*)d_in[12];
    const float* bvy = (const float*)d_in[13];
    const float* gx  = (const float*)d_in[14];
    const float* gy  = (const float*)d_in[15];
    float* out = (float*)d_out;

    cudaFuncSetAttribute(attn_kernel, cudaFuncAttributeMaxDynamicSharedMemorySize, ATTN_SMEM);

    dim3 pgrid(NN / 64, 320 / 64, 2 * BB);
    proj_tc_kernel<<<pgrid, 256>>>(x, y, wqx, bqx, wkx, bkx, wvx, bvx,
                                   wqy, bqy, wky, bky, wvy, bvy);

    dim3 agrid(NN / 64, BB, 2);
    attn_kernel<<<agrid, 256, ATTN_SMEM>>>(x, y, gx, gy, out);
}

// round 16
// speedup vs baseline: 1.0163x; 1.0163x over previous
#include <cuda_runtime.h>
#include <cuda_bf16.h>
#include <cuda_fp16.h>
#include <math.h>

#define BB 8
#define CC 256
#define NN 2304   // 48*48
#define NT (NN/32)

typedef unsigned long long u64;
typedef unsigned int u32;

__device__ __forceinline__ u32 s2u(const void* p) {
    return (u32)__cvta_generic_to_shared(p);
}
__device__ __forceinline__ void ldsm4(u32* r, u32 a) {
    asm volatile("ldmatrix.sync.aligned.m8n8.x4.shared.b16 {%0,%1,%2,%3},[%4];"
        : "=r"(r[0]), "=r"(r[1]), "=r"(r[2]), "=r"(r[3]) : "r"(a));
}
__device__ __forceinline__ void ldsm4t(u32* r, u32 a) {
    asm volatile("ldmatrix.sync.aligned.m8n8.x4.trans.shared.b16 {%0,%1,%2,%3},[%4];"
        : "=r"(r[0]), "=r"(r[1]), "=r"(r[2]), "=r"(r[3]) : "r"(a));
}
__device__ __forceinline__ void mma_bf16(float* c, const u32* a, u32 b0, u32 b1) {
    asm volatile("mma.sync.aligned.m16n8k16.row.col.f32.bf16.bf16.f32 "
        "{%0,%1,%2,%3},{%4,%5,%6,%7},{%8,%9},{%0,%1,%2,%3};"
        : "+f"(c[0]), "+f"(c[1]), "+f"(c[2]), "+f"(c[3])
        : "r"(a[0]), "r"(a[1]), "r"(a[2]), "r"(a[3]), "r"(b0), "r"(b1));
}
__device__ __forceinline__ void mma_f16(float* c, const u32* a, u32 b0, u32 b1) {
    asm volatile("mma.sync.aligned.m16n8k16.row.col.f32.f16.f16.f32 "
        "{%0,%1,%2,%3},{%4,%5,%6,%7},{%8,%9},{%0,%1,%2,%3};"
        : "+f"(c[0]), "+f"(c[1]), "+f"(c[2]), "+f"(c[3])
        : "r"(a[0]), "r"(a[1]), "r"(a[2]), "r"(a[3]), "r"(b0), "r"(b1));
}
// packs {lo -> bits[15:0], hi -> bits[31:16]}
__device__ __forceinline__ u32 cvt_bf16x2(float hi, float lo) {
    u32 r; asm("cvt.rn.bf16x2.f32 %0,%1,%2;" : "=r"(r) : "f"(hi), "f"(lo)); return r;
}
__device__ __forceinline__ u32 cvt_f16x2(float hi, float lo) {
    u32 r; asm("cvt.rn.f16x2.f32 %0,%1,%2;" : "=r"(r) : "f"(hi), "f"(lo)); return r;
}
__device__ __forceinline__ void cpasync16(u32 dst, const void* src) {
    asm volatile("cp.async.cg.shared.global [%0],[%1],16;" :: "r"(dst), "l"(src));
}
__device__ __forceinline__ void cpcommit() { asm volatile("cp.async.commit_group;"); }
__device__ __forceinline__ void cpwait1()  { asm volatile("cp.async.wait_group 1;"); }
__device__ __forceinline__ void cpwait0()  { asm volatile("cp.async.wait_group 0;"); }

// Scratch (cudaMalloc banned -> __device__ globals).
// Q/K: fp16 (fp16 products exact in fp32 accum; logit err ~4e-3, safe).
// V:   bf16 (P reaches e^28 -> P must be bf16; V matches).
// branch 0: Q/K from y-projections (attn2), V = v1 (from x)  -> out1
// branch 1: Q/K from x-projections (attn1), V = v2 (from y)  -> out2
__device__ __half        g_qf[2][BB][NN][32];
__device__ __half        g_kf[2][BB][NN][32];
__device__ __nv_bfloat16 g_vb[2][BB][NN][CC];

// split fp32 -> bf16 hi/lo, pack 8 values into 16B stores
__device__ __forceinline__ void split_store8(const float* v,
                                             __nv_bfloat16* hd, __nv_bfloat16* ld) {
    u32 hw[4], lw[4];
    #pragma unroll
    for (int i = 0; i < 4; i++) {
        float a = v[2*i], b = v[2*i+1];
        __nv_bfloat16 ha = __float2bfloat16(a), hb = __float2bfloat16(b);
        hw[i] = cvt_bf16x2(__bfloat162float(hb), __bfloat162float(ha));
        lw[i] = cvt_bf16x2(b - __bfloat162float(hb), a - __bfloat162float(ha));
    }
    *(uint4*)hd = make_uint4(hw[0], hw[1], hw[2], hw[3]);
    *(uint4*)ld = make_uint4(lw[0], lw[1], lw[2], lw[3]);
}
// fp32 -> fp16, pack 8 values into one 16B store
__device__ __forceinline__ void f16_store8(const float* v, void* d) {
    u32 hw[4];
    #pragma unroll
    for (int i = 0; i < 4; i++)
        hw[i] = cvt_f16x2(v[2*i+1], v[2*i]);
    *(uint4*)d = make_uint4(hw[0], hw[1], hw[2], hw[3]);
}

// ---------------------------------------------------------------------------
// Tensor-core projection GEMM (unchanged from R14).
// Q/K blocks (O0==0): split-bf16, 3 mma passes. V blocks: single-pass fp16.
// ---------------------------------------------------------------------------
__global__ __launch_bounds__(256) void proj_tc_kernel(
    const float* __restrict__ x, const float* __restrict__ y,
    const float* __restrict__ wqx, const float* __restrict__ bqx,
    const float* __restrict__ wkx, const float* __restrict__ bkx,
    const float* __restrict__ wvx, const float* __restrict__ bvx,
    const float* __restrict__ wqy, const float* __restrict__ bqy,
    const float* __restrict__ wky, const float* __restrict__ bky,
    const float* __restrict__ wvy, const float* __restrict__ bvy)
{
    const int inp = blockIdx.z >> 3;
    const int b   = blockIdx.z & 7;
    const int n0  = blockIdx.x * 64;
    const int O0  = blockIdx.y * 64;
    const bool isQK = (O0 == 0);

    const float* in = inp ? y : x;
    const float* wq = inp ? wqy : wqx;  const float* bq = inp ? bqy : bqx;
    const float* wk = inp ? wky : wkx;  const float* bk = inp ? bky : bkx;
    const float* wv = inp ? wvy : wvx;  const float* bv = inp ? bvy : bvx;
    const int qb = inp ? 0 : 1;
    const int vb = inp ? 1 : 0;

    __shared__ __align__(16) char smemraw[19968];
    __nv_bfloat16* sWh = (__nv_bfloat16*)smemraw;          // qk: bf16-hi | v: fp16
    __nv_bfloat16* sWl = sWh + 64 * 40;
    __nv_bfloat16* sXh = sWl + 64 * 40;                    // qk: bf16-hi | v: fp16
    __nv_bfloat16* sXl = sXh + 32 * 72;
    float* sT = (float*)smemraw;          // [64][68]

    const int tid = threadIdx.x;
    const int w = tid >> 5, l = tid & 31;
    const int rg = w & 3, ng = w >> 2;
    const int grp = l >> 2, t4 = l & 3;
    const int lrow = l & 15;
    const int hi8 = (l & 16) ? 8 : 0;

    const int wrow_i = tid >> 2;
    const int wcseg  = (tid & 3) * 8;
    const int og = O0 + wrow_i;
    const float* wrow = (og < 32) ? (wq + (size_t)og * CC)
                      : (og < 64) ? (wk + (size_t)(og - 32) * CC)
                                  : (wv + (size_t)(og - 64) * CC);
    const int xrow_i = tid >> 3;
    const int xnseg  = (tid & 7) * 8;
    const float* xbase = in + ((size_t)b * CC + xrow_i) * NN + n0 + xnseg;

    float acc[4][4];
    #pragma unroll
    for (int t = 0; t < 4; t++)
        #pragma unroll
        for (int i = 0; i < 4; i++) acc[t][i] = 0.f;

    for (int c0 = 0; c0 < CC; c0 += 32) {
        {
            float4 wa = *(const float4*)(wrow + c0 + wcseg);
            float4 wb = *(const float4*)(wrow + c0 + wcseg + 4);
            float v[8] = {wa.x, wa.y, wa.z, wa.w, wb.x, wb.y, wb.z, wb.w};
            if (isQK) split_store8(v, &sWh[wrow_i * 40 + wcseg], &sWl[wrow_i * 40 + wcseg]);
            else      f16_store8(v, &sWh[wrow_i * 40 + wcseg]);
        }
        {
            const float* xp = xbase + (size_t)c0 * NN;
            float4 xa = *(const float4*)xp;
            float4 xc = *(const float4*)(xp + 4);
            float v[8] = {xa.x, xa.y, xa.z, xa.w, xc.x, xc.y, xc.z, xc.w};
            if (isQK) split_store8(v, &sXh[xrow_i * 72 + xnseg], &sXl[xrow_i * 72 + xnseg]);
            else      f16_store8(v, &sXh[xrow_i * 72 + xnseg]);
        }
        __syncthreads();

        if (isQK) {
            #pragma unroll
            for (int kc = 0; kc < 2; kc++) {
                u32 ah[4], al[4];
                ldsm4(ah, s2u(&sWh[(rg * 16 + lrow) * 40 + kc * 16 + hi8]));
                ldsm4(al, s2u(&sWl[(rg * 16 + lrow) * 40 + kc * 16 + hi8]));
                #pragma unroll
                for (int sp = 0; sp < 2; sp++) {
                    u32 bh[4], bl[4];
                    int xoff = (kc * 16 + lrow) * 72 + ng * 32 + sp * 16 + hi8;
                    ldsm4t(bh, s2u(&sXh[xoff]));
                    ldsm4t(bl, s2u(&sXl[xoff]));
                    int t = sp * 2;
                    mma_bf16(acc[t], ah, bh[0], bh[1]);
                    mma_bf16(acc[t], ah, bl[0], bl[1]);
                    mma_bf16(acc[t], al, bh[0], bh[1]);
                    mma_bf16(acc[t+1], ah, bh[2], bh[3]);
                    mma_bf16(acc[t+1], ah, bl[2], bl[3]);
                    mma_bf16(acc[t+1], al, bh[2], bh[3]);
                }
            }
        } else {
            #pragma unroll
            for (int kc = 0; kc < 2; kc++) {
                u32 ah[4];
                ldsm4(ah, s2u(&sWh[(rg * 16 + lrow) * 40 + kc * 16 + hi8]));
                #pragma unroll
                for (int sp = 0; sp < 2; sp++) {
                    u32 bh[4];
                    int xoff = (kc * 16 + lrow) * 72 + ng * 32 + sp * 16 + hi8;
                    ldsm4t(bh, s2u(&sXh[xoff]));
                    int t = sp * 2;
                    mma_f16(acc[t],   ah, bh[0], bh[1]);
                    mma_f16(acc[t+1], ah, bh[2], bh[3]);
                }
            }
        }
        __syncthreads();
    }

    const int ol0 = rg * 16 + grp, ol1 = ol0 + 8;
    float bias0, bias1;
    {
        int o0g = O0 + ol0, o1g = O0 + ol1;
        bias0 = (o0g < 32) ? bq[o0g] : (o0g < 64) ? bk[o0g - 32] : bv[o0g - 64];
        bias1 = (o1g < 32) ? bq[o1g] : (o1g < 64) ? bk[o1g - 32] : bv[o1g - 64];
    }

    // transpose via smem: sT[n_local][o_local]
    #pragma unroll
    for (int t = 0; t < 4; t++) {
        int nl = ng * 32 + (t >> 1) * 16 + (t & 1) * 8 + 2 * t4;
        sT[nl * 68 + ol0]       = acc[t][0] + bias0;
        sT[(nl + 1) * 68 + ol0] = acc[t][1] + bias0;
        sT[nl * 68 + ol1]       = acc[t][2] + bias1;
        sT[(nl + 1) * 68 + ol1] = acc[t][3] + bias1;
    }
    __syncthreads();

    {
        int row  = tid >> 2;
        int oseg = (tid & 3) * 16;
        int n = n0 + row;
        float4 v0 = *(const float4*)&sT[row * 68 + oseg];
        float4 v1 = *(const float4*)&sT[row * 68 + oseg + 4];
        float4 v2 = *(const float4*)&sT[row * 68 + oseg + 8];
        float4 v3 = *(const float4*)&sT[row * 68 + oseg + 12];
        float vv[16] = {v0.x,v0.y,v0.z,v0.w, v1.x,v1.y,v1.z,v1.w,
                        v2.x,v2.y,v2.z,v2.w, v3.x,v3.y,v3.z,v3.w};
        if (isQK) {
            // q/k path: fp16
            u32 hw[8];
            #pragma unroll
            for (int i = 0; i < 8; i++)
                hw[i] = cvt_f16x2(vv[2*i+1], vv[2*i]);
            if (oseg < 32) {
                *(uint4*)&g_qf[qb][b][n][oseg]     = make_uint4(hw[0],hw[1],hw[2],hw[3]);
                *(uint4*)&g_qf[qb][b][n][oseg + 8] = make_uint4(hw[4],hw[5],hw[6],hw[7]);
            } else {
                int ko = oseg - 32;
                *(uint4*)&g_kf[qb][b][n][ko]     = make_uint4(hw[0],hw[1],hw[2],hw[3]);
                *(uint4*)&g_kf[qb][b][n][ko + 8] = make_uint4(hw[4],hw[5],hw[6],hw[7]);
            }
        } else {
            int cb = O0 - 64 + oseg;
            u32 hw[8];
            #pragma unroll
            for (int i = 0; i < 8; i++)
                hw[i] = cvt_bf16x2(vv[2*i+1], vv[2*i]);
            *(uint4*)&g_vb[vb][b][n][cb]     = make_uint4(hw[0],hw[1],hw[2],hw[3]);
            *(uint4*)&g_vb[vb][b][n][cb + 8] = make_uint4(hw[4],hw[5],hw[6],hw[7]);
        }
    }
}

// ---------------------------------------------------------------------------
// Tensor-core fused attention. NEW: S/exp computed ONCE per (rg,j) — warp
// (rg,ch) does S only for j in [ch*16, ch*16+16) (4 mma + 8 exp), stores
// bf16 P to a double-buffered smem tile, pair-syncs via named barrier, then
// both warps ldsm the full P[16q][32j] as A-fragments for PV.
// R12 loop skeleton (prefetch -> cpwait1 -> sync -> compute -> trailing sync).
// smem: sQ[64][40] f16 (5120) | sK 2x[32][40] f16 (5120)
//       | sV 2x[32][264] bf16 (33792) | sP 2x[64][40] bf16 (10240)
//       | sL[2][64] f32 (512)  => 54784B
// ---------------------------------------------------------------------------
#define ATTN_SMEM 54784

__global__ __launch_bounds__(256, 2) void attn_kernel(
    const float* __restrict__ x, const float* __restrict__ y,
    const float* __restrict__ gx, const float* __restrict__ gy,
    float* __restrict__ out)
{
    const int br  = blockIdx.z;
    const int b   = blockIdx.y;
    const int i0  = blockIdx.x * 64;
    const int tid = threadIdx.x;
    const int w   = tid >> 5;
    const int l   = tid & 31;
    const int rg  = w & 3;
    const int ch  = w >> 2;
    const int grp = l >> 2;
    const int t4  = l & 3;
    const int q0  = rg * 16;

    const float* res = br ? y : x;
    const float* gmm = br ? gy : gx;
    float* outp = out + (size_t)br * BB * CC * NN;

    extern __shared__ __align__(16) char sm[];
    __half*        sQ = (__half*)sm;                   // [64][40]
    __half*        sK = (__half*)(sm + 5120);          // 2 x [32][40]
    __nv_bfloat16* sV = (__nv_bfloat16*)(sm + 10240);  // 2 x [32][264]
    __nv_bfloat16* sP = (__nv_bfloat16*)(sm + 44032);  // 2 x [64][40]
    float*         sL = (float*)(sm + 54272);          // [2][64]

    // Stage Q: 64 rows x 32 fp16
    {
        int row = tid >> 2, c8 = (tid & 3) * 8;
        *(float4*)&sQ[row * 40 + c8] = *(const float4*)&g_qf[br][b][i0 + row][c8];
    }
    __syncthreads();

    // Persistent Q fragments: rows q0..q0+15, k chunks 0/1
    u32 qf[2][4];
    {
        int row = q0 + (l & 15);
        int cofs = (l & 16) ? 8 : 0;
        #pragma unroll
        for (int kc = 0; kc < 2; kc++)
            ldsm4(qf[kc], s2u(&sQ[row * 40 + kc * 16 + cofs]));
    }

    const __half*        kg = &g_kf[br][b][0][0];
    const __nv_bfloat16* vg = &g_vb[br][b][0][0];

    const int krow = tid >> 2;          // tid<128: K rows 0..31
    const int kc8  = (tid & 3) * 8;

    float acc[16][4];
    #pragma unroll
    for (int t = 0; t < 16; t++)
        #pragma unroll
        for (int i = 0; i < 4; i++) acc[t][i] = 0.f;
    float lsA = 0.f, lsB = 0.f;

    // prologue: loads for tile 0 into buf 0
    {
        if (tid < 128)
            cpasync16(s2u(&sK[krow * 40 + kc8]), kg + (size_t)krow * 32 + kc8);
        #pragma unroll
        for (int it = 0; it < 4; it++) {
            int idx = tid + it * 256;
            int vr = idx >> 5, vc8 = (idx & 31) * 8;
            cpasync16(s2u(&sV[vr * 264 + vc8]), vg + (size_t)vr * CC + vc8);
        }
        cpcommit();
    }

    const int ldA = (l & 16) ? 8 : 0;
    const int krA = ((l >> 4) << 3) + (l & 7);
    const int kcA = ((l >> 3) & 1) * 8;

    for (int t = 0; t < NT; t++) {
        const int buf = t & 1;
        if (t + 1 < NT) {
            const int nb = buf ^ 1;
            const int j1 = (t + 1) * 32;
            if (tid < 128)
                cpasync16(s2u(&sK[nb * 1280 + krow * 40 + kc8]),
                          kg + (size_t)(j1 + krow) * 32 + kc8);
            #pragma unroll
            for (int it = 0; it < 4; it++) {
                int idx = tid + it * 256;
                int vr = idx >> 5, vc8 = (idx & 31) * 8;
                cpasync16(s2u(&sV[nb * 8448 + vr * 264 + vc8]),
                          vg + (size_t)(j1 + vr) * CC + vc8);
            }
            cpcommit();
            cpwait1();
        } else {
            cpwait0();
        }
        __syncthreads();

        const __half*        bK  = sK + buf * 1280;
        const __nv_bfloat16* bV  = sV + buf * 8448;
        __nv_bfloat16*       bPw = sP + buf * 2560;   // write view
        const __nv_bfloat16* bPr = bPw;               // read view (same buf)

        // S phase: ONLY this warp's j half (j = ch*16 .. ch*16+15): 2 n8 tiles
        float sc[2][4];
        #pragma unroll
        for (int tt = 0; tt < 2; tt++)
            #pragma unroll
            for (int i = 0; i < 4; i++) sc[tt][i] = 0.f;

        #pragma unroll
        for (int kc = 0; kc < 2; kc++) {
            u32 k4[4];
            ldsm4(k4, s2u(&bK[(ch * 16 + krA) * 40 + kc * 16 + kcA]));
            mma_f16(sc[0], qf[kc], k4[0], k4[1]);
            mma_f16(sc[1], qf[kc], k4[2], k4[3]);
        }

        // exp (8 per thread, no duplication) + store bf16 P to smem
        #pragma unroll
        for (int tt = 0; tt < 2; tt++) {
            float e0 = __expf(sc[tt][0]);
            float e1 = __expf(sc[tt][1]);
            float e2 = __expf(sc[tt][2]);
            float e3 = __expf(sc[tt][3]);
            lsA += e0 + e1;
            lsB += e2 + e3;
            int j = ch * 16 + tt * 8 + 2 * t4;
            *(u32*)&bPw[(q0 + grp) * 40 + j]     = cvt_bf16x2(e1, e0);
            *(u32*)&bPw[(q0 + 8 + grp) * 40 + j] = cvt_bf16x2(e3, e2);
        }

        // pair barrier: warps (rg,0) and (rg,1) exchange their P halves
        asm volatile("bar.sync %0, %1;" :: "r"(rg + 1), "r"(64) : "memory");

        // load full P[16q][32j] as A-fragments
        u32 pa[2][4];
        {
            int row = q0 + (l & 15);
            #pragma unroll
            for (int kj = 0; kj < 2; kj++)
                ldsm4(pa[kj], s2u(&bPr[row * 40 + kj * 16 + ldA]));
        }

        // PV: B = V frags via ldsm4t (same tile)
        #pragma unroll
        for (int g = 0; g < 8; g++) {
            int n0 = ch * 128 + g * 16 + ldA;
            #pragma unroll
            for (int kj = 0; kj < 2; kj++) {
                u32 vb4[4];
                ldsm4t(vb4, s2u(&bV[(kj * 16 + (l & 15)) * 264 + n0]));
                mma_bf16(acc[g * 2],     pa[kj], vb4[0], vb4[1]);
                mma_bf16(acc[g * 2 + 1], pa[kj], vb4[2], vb4[3]);
            }
        }
        __syncthreads();   // all reads of buf done before it is overwritten
    }

    // lsum: quad reduce gives this warp's j-half sum; combine halves via smem
    lsA += __shfl_xor_sync(0xffffffffu, lsA, 1);
    lsA += __shfl_xor_sync(0xffffffffu, lsA, 2);
    lsB += __shfl_xor_sync(0xffffffffu, lsB, 1);
    lsB += __shfl_xor_sync(0xffffffffu, lsB, 2);
    if (t4 == 0) {
        sL[ch * 64 + q0 + grp]     = lsA;
        sL[ch * 64 + q0 + 8 + grp] = lsB;
    }
    __syncthreads();

    const float g = gmm[0];
    float L0 = sL[q0 + grp]     + sL[64 + q0 + grp];
    float L1 = sL[q0 + 8 + grp] + sL[64 + q0 + 8 + grp];
    float rl0 = g / L0, rl1 = g / L1;
    int ir0 = i0 + q0 + grp;
    int ir1 = ir0 + 8;
    #pragma unroll
    for (int t = 0; t < 16; t++) {
        int c0 = ch * 128 + t * 8 + 2 * t4;
        size_t base = ((size_t)b * CC + c0) * NN;
        outp[base + ir0]      = acc[t][0] * rl0 + res[base + ir0];
        outp[base + NN + ir0] = acc[t][1] * rl0 + res[base + NN + ir0];
        outp[base + ir1]      = acc[t][2] * rl1 + res[base + ir1];
        outp[base + NN + ir1] = acc[t][3] * rl1 + res[base + NN + ir1];
    }
}

// ---------------------------------------------------------------------------

extern "C" void kernel_launch(void* const* d_in, const int* in_sizes, int n_in,
                              void* d_out, int out_size)
{
    const float* x   = (const float*)d_in[0];
    const float* y   = (const float*)d_in[1];
    const float* wqx = (const float*)d_in[2];
    const float* bqx = (const float*)d_in[3];
    const float* wkx = (const float*)d_in[4];
    const float* bkx = (const float*)d_in[5];
    const float* wvx = (const float*)d_in[6];
    const float* bvx = (const float*)d_in[7];
    const float* wqy = (const float*)d_in[8];
    const float* bqy = (const float*)d_in[9];
    const float* wky = (const float*)d_in[10];
    const float* bky = (const float*)d_in[11];
    const float* wvy = (const float*)d_in[12];
    const float* bvy = (const float*)d_in[13];
    const float* gx  = (const float*)d_in[14];
    const float* gy  = (const float*)d_in[15];
    float* out = (float*)d_out;

    cudaFuncSetAttribute(attn_kernel, cudaFuncAttributeMaxDynamicSharedMemorySize, ATTN_SMEM);

    dim3 pgrid(NN / 64, 320 / 64, 2 * BB);
    proj_tc_kernel<<<pgrid, 256>>>(x, y, wqx, bqx, wkx, bkx, wvx, bvx,
                                   wqy, bqy, wky, bky, wvy, bvy);

    dim3 agrid(NN / 64, BB, 2);
    attn_kernel<<<agrid, 256, ATTN_SMEM>>>(x, y, gx, gy, out);
}

// round 17
// speedup vs baseline: 1.0641x; 1.0470x over previous
#include <cuda_runtime.h>
#include <cuda_bf16.h>
#include <cuda_fp16.h>
#include <math.h>

#define BB 8
#define CC 256
#define NN 2304   // 48*48
#define NT (NN/32)

typedef unsigned long long u64;
typedef unsigned int u32;

__device__ __forceinline__ u32 s2u(const void* p) {
    return (u32)__cvta_generic_to_shared(p);
}
__device__ __forceinline__ void ldsm4(u32* r, u32 a) {
    asm volatile("ldmatrix.sync.aligned.m8n8.x4.shared.b16 {%0,%1,%2,%3},[%4];"
        : "=r"(r[0]), "=r"(r[1]), "=r"(r[2]), "=r"(r[3]) : "r"(a));
}
__device__ __forceinline__ void ldsm2(u32* r, u32 a) {
    asm volatile("ldmatrix.sync.aligned.m8n8.x2.shared.b16 {%0,%1},[%2];"
        : "=r"(r[0]), "=r"(r[1]) : "r"(a));
}
__device__ __forceinline__ void ldsm4t(u32* r, u32 a) {
    asm volatile("ldmatrix.sync.aligned.m8n8.x4.trans.shared.b16 {%0,%1,%2,%3},[%4];"
        : "=r"(r[0]), "=r"(r[1]), "=r"(r[2]), "=r"(r[3]) : "r"(a));
}
__device__ __forceinline__ void mma_bf16(float* c, const u32* a, u32 b0, u32 b1) {
    asm volatile("mma.sync.aligned.m16n8k16.row.col.f32.bf16.bf16.f32 "
        "{%0,%1,%2,%3},{%4,%5,%6,%7},{%8,%9},{%0,%1,%2,%3};"
        : "+f"(c[0]), "+f"(c[1]), "+f"(c[2]), "+f"(c[3])
        : "r"(a[0]), "r"(a[1]), "r"(a[2]), "r"(a[3]), "r"(b0), "r"(b1));
}
__device__ __forceinline__ void mma_f16(float* c, const u32* a, u32 b0, u32 b1) {
    asm volatile("mma.sync.aligned.m16n8k16.row.col.f32.f16.f16.f32 "
        "{%0,%1,%2,%3},{%4,%5,%6,%7},{%8,%9},{%0,%1,%2,%3};"
        : "+f"(c[0]), "+f"(c[1]), "+f"(c[2]), "+f"(c[3])
        : "r"(a[0]), "r"(a[1]), "r"(a[2]), "r"(a[3]), "r"(b0), "r"(b1));
}
// packs {lo -> bits[15:0], hi -> bits[31:16]}
__device__ __forceinline__ u32 cvt_bf16x2(float hi, float lo) {
    u32 r; asm("cvt.rn.bf16x2.f32 %0,%1,%2;" : "=r"(r) : "f"(hi), "f"(lo)); return r;
}
__device__ __forceinline__ u32 cvt_f16x2(float hi, float lo) {
    u32 r; asm("cvt.rn.f16x2.f32 %0,%1,%2;" : "=r"(r) : "f"(hi), "f"(lo)); return r;
}
__device__ __forceinline__ void cpasync16(u32 dst, const void* src) {
    asm volatile("cp.async.cg.shared.global [%0],[%1],16;" :: "r"(dst), "l"(src));
}
__device__ __forceinline__ void cpcommit() { asm volatile("cp.async.commit_group;"); }
__device__ __forceinline__ void cpwait1()  { asm volatile("cp.async.wait_group 1;"); }
__device__ __forceinline__ void cpwait0()  { asm volatile("cp.async.wait_group 0;"); }

// Scratch (cudaMalloc banned -> __device__ globals).
// Q/K: fp16 (fp16 products exact in fp32 accum; logit err ~4e-3, safe).
// V:   bf16 (P reaches e^28 -> P must be bf16; V matches).
// branch 0: Q/K from y-projections (attn2), V = v1 (from x)  -> out1
// branch 1: Q/K from x-projections (attn1), V = v2 (from y)  -> out2
__device__ __half        g_qf[2][BB][NN][32];
__device__ __half        g_kf[2][BB][NN][32];
__device__ __nv_bfloat16 g_vb[2][BB][NN][CC];

// split fp32 -> bf16 hi/lo, pack 8 values into 16B stores
__device__ __forceinline__ void split_store8(const float* v,
                                             __nv_bfloat16* hd, __nv_bfloat16* ld) {
    u32 hw[4], lw[4];
    #pragma unroll
    for (int i = 0; i < 4; i++) {
        float a = v[2*i], b = v[2*i+1];
        __nv_bfloat16 ha = __float2bfloat16(a), hb = __float2bfloat16(b);
        hw[i] = cvt_bf16x2(__bfloat162float(hb), __bfloat162float(ha));
        lw[i] = cvt_bf16x2(b - __bfloat162float(hb), a - __bfloat162float(ha));
    }
    *(uint4*)hd = make_uint4(hw[0], hw[1], hw[2], hw[3]);
    *(uint4*)ld = make_uint4(lw[0], lw[1], lw[2], lw[3]);
}
// fp32 -> fp16, pack 8 values into one 16B store
__device__ __forceinline__ void f16_store8(const float* v, void* d) {
    u32 hw[4];
    #pragma unroll
    for (int i = 0; i < 4; i++)
        hw[i] = cvt_f16x2(v[2*i+1], v[2*i]);
    *(uint4*)d = make_uint4(hw[0], hw[1], hw[2], hw[3]);
}

// ---------------------------------------------------------------------------
// Tensor-core projection GEMM (unchanged from R14).
// Q/K blocks (O0==0): split-bf16, 3 mma passes. V blocks: single-pass fp16.
// ---------------------------------------------------------------------------
__global__ __launch_bounds__(256) void proj_tc_kernel(
    const float* __restrict__ x, const float* __restrict__ y,
    const float* __restrict__ wqx, const float* __restrict__ bqx,
    const float* __restrict__ wkx, const float* __restrict__ bkx,
    const float* __restrict__ wvx, const float* __restrict__ bvx,
    const float* __restrict__ wqy, const float* __restrict__ bqy,
    const float* __restrict__ wky, const float* __restrict__ bky,
    const float* __restrict__ wvy, const float* __restrict__ bvy)
{
    const int inp = blockIdx.z >> 3;
    const int b   = blockIdx.z & 7;
    const int n0  = blockIdx.x * 64;
    const int O0  = blockIdx.y * 64;
    const bool isQK = (O0 == 0);

    const float* in = inp ? y : x;
    const float* wq = inp ? wqy : wqx;  const float* bq = inp ? bqy : bqx;
    const float* wk = inp ? wky : wkx;  const float* bk = inp ? bky : bkx;
    const float* wv = inp ? wvy : wvx;  const float* bv = inp ? bvy : bvx;
    const int qb = inp ? 0 : 1;
    const int vb = inp ? 1 : 0;

    __shared__ __align__(16) char smemraw[19968];
    __nv_bfloat16* sWh = (__nv_bfloat16*)smemraw;          // qk: bf16-hi | v: fp16
    __nv_bfloat16* sWl = sWh + 64 * 40;
    __nv_bfloat16* sXh = sWl + 64 * 40;                    // qk: bf16-hi | v: fp16
    __nv_bfloat16* sXl = sXh + 32 * 72;
    float* sT = (float*)smemraw;          // [64][68]

    const int tid = threadIdx.x;
    const int w = tid >> 5, l = tid & 31;
    const int rg = w & 3, ng = w >> 2;
    const int grp = l >> 2, t4 = l & 3;
    const int lrow = l & 15;
    const int hi8 = (l & 16) ? 8 : 0;

    const int wrow_i = tid >> 2;
    const int wcseg  = (tid & 3) * 8;
    const int og = O0 + wrow_i;
    const float* wrow = (og < 32) ? (wq + (size_t)og * CC)
                      : (og < 64) ? (wk + (size_t)(og - 32) * CC)
                                  : (wv + (size_t)(og - 64) * CC);
    const int xrow_i = tid >> 3;
    const int xnseg  = (tid & 7) * 8;
    const float* xbase = in + ((size_t)b * CC + xrow_i) * NN + n0 + xnseg;

    float acc[4][4];
    #pragma unroll
    for (int t = 0; t < 4; t++)
        #pragma unroll
        for (int i = 0; i < 4; i++) acc[t][i] = 0.f;

    for (int c0 = 0; c0 < CC; c0 += 32) {
        {
            float4 wa = *(const float4*)(wrow + c0 + wcseg);
            float4 wb = *(const float4*)(wrow + c0 + wcseg + 4);
            float v[8] = {wa.x, wa.y, wa.z, wa.w, wb.x, wb.y, wb.z, wb.w};
            if (isQK) split_store8(v, &sWh[wrow_i * 40 + wcseg], &sWl[wrow_i * 40 + wcseg]);
            else      f16_store8(v, &sWh[wrow_i * 40 + wcseg]);
        }
        {
            const float* xp = xbase + (size_t)c0 * NN;
            float4 xa = *(const float4*)xp;
            float4 xc = *(const float4*)(xp + 4);
            float v[8] = {xa.x, xa.y, xa.z, xa.w, xc.x, xc.y, xc.z, xc.w};
            if (isQK) split_store8(v, &sXh[xrow_i * 72 + xnseg], &sXl[xrow_i * 72 + xnseg]);
            else      f16_store8(v, &sXh[xrow_i * 72 + xnseg]);
        }
        __syncthreads();

        if (isQK) {
            #pragma unroll
            for (int kc = 0; kc < 2; kc++) {
                u32 ah[4], al[4];
                ldsm4(ah, s2u(&sWh[(rg * 16 + lrow) * 40 + kc * 16 + hi8]));
                ldsm4(al, s2u(&sWl[(rg * 16 + lrow) * 40 + kc * 16 + hi8]));
                #pragma unroll
                for (int sp = 0; sp < 2; sp++) {
                    u32 bh[4], bl[4];
                    int xoff = (kc * 16 + lrow) * 72 + ng * 32 + sp * 16 + hi8;
                    ldsm4t(bh, s2u(&sXh[xoff]));
                    ldsm4t(bl, s2u(&sXl[xoff]));
                    int t = sp * 2;
                    mma_bf16(acc[t], ah, bh[0], bh[1]);
                    mma_bf16(acc[t], ah, bl[0], bl[1]);
                    mma_bf16(acc[t], al, bh[0], bh[1]);
                    mma_bf16(acc[t+1], ah, bh[2], bh[3]);
                    mma_bf16(acc[t+1], ah, bl[2], bl[3]);
                    mma_bf16(acc[t+1], al, bh[2], bh[3]);
                }
            }
        } else {
            #pragma unroll
            for (int kc = 0; kc < 2; kc++) {
                u32 ah[4];
                ldsm4(ah, s2u(&sWh[(rg * 16 + lrow) * 40 + kc * 16 + hi8]));
                #pragma unroll
                for (int sp = 0; sp < 2; sp++) {
                    u32 bh[4];
                    int xoff = (kc * 16 + lrow) * 72 + ng * 32 + sp * 16 + hi8;
                    ldsm4t(bh, s2u(&sXh[xoff]));
                    int t = sp * 2;
                    mma_f16(acc[t],   ah, bh[0], bh[1]);
                    mma_f16(acc[t+1], ah, bh[2], bh[3]);
                }
            }
        }
        __syncthreads();
    }

    const int ol0 = rg * 16 + grp, ol1 = ol0 + 8;
    float bias0, bias1;
    {
        int o0g = O0 + ol0, o1g = O0 + ol1;
        bias0 = (o0g < 32) ? bq[o0g] : (o0g < 64) ? bk[o0g - 32] : bv[o0g - 64];
        bias1 = (o1g < 32) ? bq[o1g] : (o1g < 64) ? bk[o1g - 32] : bv[o1g - 64];
    }

    // transpose via smem: sT[n_local][o_local]
    #pragma unroll
    for (int t = 0; t < 4; t++) {
        int nl = ng * 32 + (t >> 1) * 16 + (t & 1) * 8 + 2 * t4;
        sT[nl * 68 + ol0]       = acc[t][0] + bias0;
        sT[(nl + 1) * 68 + ol0] = acc[t][1] + bias0;
        sT[nl * 68 + ol1]       = acc[t][2] + bias1;
        sT[(nl + 1) * 68 + ol1] = acc[t][3] + bias1;
    }
    __syncthreads();

    {
        int row  = tid >> 2;
        int oseg = (tid & 3) * 16;
        int n = n0 + row;
        float4 v0 = *(const float4*)&sT[row * 68 + oseg];
        float4 v1 = *(const float4*)&sT[row * 68 + oseg + 4];
        float4 v2 = *(const float4*)&sT[row * 68 + oseg + 8];
        float4 v3 = *(const float4*)&sT[row * 68 + oseg + 12];
        float vv[16] = {v0.x,v0.y,v0.z,v0.w, v1.x,v1.y,v1.z,v1.w,
                        v2.x,v2.y,v2.z,v2.w, v3.x,v3.y,v3.z,v3.w};
        if (isQK) {
            u32 hw[8];
            #pragma unroll
            for (int i = 0; i < 8; i++)
                hw[i] = cvt_f16x2(vv[2*i+1], vv[2*i]);
            if (oseg < 32) {
                *(uint4*)&g_qf[qb][b][n][oseg]     = make_uint4(hw[0],hw[1],hw[2],hw[3]);
                *(uint4*)&g_qf[qb][b][n][oseg + 8] = make_uint4(hw[4],hw[5],hw[6],hw[7]);
            } else {
                int ko = oseg - 32;
                *(uint4*)&g_kf[qb][b][n][ko]     = make_uint4(hw[0],hw[1],hw[2],hw[3]);
                *(uint4*)&g_kf[qb][b][n][ko + 8] = make_uint4(hw[4],hw[5],hw[6],hw[7]);
            }
        } else {
            int cb = O0 - 64 + oseg;
            u32 hw[8];
            #pragma unroll
            for (int i = 0; i < 8; i++)
                hw[i] = cvt_bf16x2(vv[2*i+1], vv[2*i]);
            *(uint4*)&g_vb[vb][b][n][cb]     = make_uint4(hw[0],hw[1],hw[2],hw[3]);
            *(uint4*)&g_vb[vb][b][n][cb + 8] = make_uint4(hw[4],hw[5],hw[6],hw[7]);
        }
    }
}

// ---------------------------------------------------------------------------
// Tensor-core fused attention, 512 threads / 128 queries per CTA.
// 16 warps = qg(0..3) x chq(0..3). Warp owns 32q x 64c; V fragments loaded
// once and reused across both 16-row q-subtiles (V smem traffic halved, and
// K/V global traffic halved vs 64q CTAs). S computed once per (q,j): warp
// (qg,chq) does S[32q][j-quarter 8j] (4 mma + 8 exp), bf16 P exchanged via
// sP + named barrier (4 warps sharing qg). No-max softmax.
// smem: sQ[128][40] f16 (10240) | sK 2x[32][40] f16 (5120)
//     | sV 2x[32][264] bf16 (33792) | sP 2x[128][40] bf16 (20480)
//     | sL[4][128] f32 (2048)  => 71680B
// ---------------------------------------------------------------------------
#define ATTN_SMEM 71680

__global__ __launch_bounds__(512, 1) void attn_kernel(
    const float* __restrict__ x, const float* __restrict__ y,
    const float* __restrict__ gx, const float* __restrict__ gy,
    float* __restrict__ out)
{
    const int br  = blockIdx.z;
    const int b   = blockIdx.y;
    const int i0  = blockIdx.x * 128;
    const int tid = threadIdx.x;
    const int w   = tid >> 5;
    const int l   = tid & 31;
    const int qg  = w & 3;
    const int chq = w >> 2;          // 0..3: 64-channel quarter AND 8-j S slice
    const int grp = l >> 2;
    const int t4  = l & 3;
    const int q0  = qg * 32;

    const float* res = br ? y : x;
    const float* gmm = br ? gy : gx;
    float* outp = out + (size_t)br * BB * CC * NN;

    extern __shared__ __align__(16) char sm[];
    __half*        sQ = (__half*)sm;                   // [128][40]
    __half*        sK = (__half*)(sm + 10240);         // 2 x [32][40]
    __nv_bfloat16* sV = (__nv_bfloat16*)(sm + 15360);  // 2 x [32][264]
    __nv_bfloat16* sP = (__nv_bfloat16*)(sm + 49152);  // 2 x [128][40]
    float*         sL = (float*)(sm + 69632);          // [4][128]

    // Stage Q: 128 rows x 32 fp16 (512 chunks, 1 per thread)
    {
        int row = tid >> 2, c8 = (tid & 3) * 8;
        *(float4*)&sQ[row * 40 + c8] = *(const float4*)&g_qf[br][b][i0 + row][c8];
    }
    __syncthreads();

    // Persistent Q fragments: 2 q-subtiles (q0, q0+16), k chunks 0/1
    u32 qf[2][2][4];
    {
        int cofs = (l & 16) ? 8 : 0;
        #pragma unroll
        for (int qs = 0; qs < 2; qs++) {
            int row = q0 + qs * 16 + (l & 15);
            #pragma unroll
            for (int kc = 0; kc < 2; kc++)
                ldsm4(qf[qs][kc], s2u(&sQ[row * 40 + kc * 16 + cofs]));
        }
    }

    const __half*        kg = &g_kf[br][b][0][0];
    const __nv_bfloat16* vg = &g_vb[br][b][0][0];

    const int krow = tid >> 2;          // tid<128: K rows 0..31
    const int kc8  = (tid & 3) * 8;

    float acc[2][8][4];
    #pragma unroll
    for (int qs = 0; qs < 2; qs++)
        #pragma unroll
        for (int t = 0; t < 8; t++)
            #pragma unroll
            for (int i = 0; i < 4; i++) acc[qs][t][i] = 0.f;
    float lsA0 = 0.f, lsB0 = 0.f, lsA1 = 0.f, lsB1 = 0.f;

    // prologue: loads for tile 0 into buf 0
    {
        if (tid < 128)
            cpasync16(s2u(&sK[krow * 40 + kc8]), kg + (size_t)krow * 32 + kc8);
        #pragma unroll
        for (int it = 0; it < 2; it++) {
            int idx = tid + it * 512;
            int vr = idx >> 5, vc8 = (idx & 31) * 8;
            cpasync16(s2u(&sV[vr * 264 + vc8]), vg + (size_t)vr * CC + vc8);
        }
        cpcommit();
    }

    const int ldA = (l & 16) ? 8 : 0;
    const int sKrow = chq * 8 + (l & 7);            // S-phase K row
    const int sKcol = ((l >> 3) & 1) * 8;           // ldsm2 col offset

    for (int t = 0; t < NT; t++) {
        const int buf = t & 1;
        if (t + 1 < NT) {
            const int nb = buf ^ 1;
            const int j1 = (t + 1) * 32;
            if (tid < 128)
                cpasync16(s2u(&sK[nb * 1280 + krow * 40 + kc8]),
                          kg + (size_t)(j1 + krow) * 32 + kc8);
            #pragma unroll
            for (int it = 0; it < 2; it++) {
                int idx = tid + it * 512;
                int vr = idx >> 5, vc8 = (idx & 31) * 8;
                cpasync16(s2u(&sV[nb * 8448 + vr * 264 + vc8]),
                          vg + (size_t)(j1 + vr) * CC + vc8);
            }
            cpcommit();
            cpwait1();
        } else {
            cpwait0();
        }
        __syncthreads();

        const __half*        bK  = sK + buf * 1280;
        const __nv_bfloat16* bV  = sV + buf * 8448;
        __nv_bfloat16*       bPw = sP + buf * 2560;
        const __nv_bfloat16* bPr = bPw;

        // S phase: this warp's 32 q rows x its 8-j slice (j = chq*8..chq*8+7)
        float sc[2][4];
        #pragma unroll
        for (int qs = 0; qs < 2; qs++)
            #pragma unroll
            for (int i = 0; i < 4; i++) sc[qs][i] = 0.f;

        #pragma unroll
        for (int kc = 0; kc < 2; kc++) {
            u32 k2[2];
            ldsm2(k2, s2u(&bK[sKrow * 40 + kc * 16 + sKcol]));
            mma_f16(sc[0], qf[0][kc], k2[0], k2[1]);
            mma_f16(sc[1], qf[1][kc], k2[0], k2[1]);
        }

        // exp (8 per thread, no duplication) + store bf16 P to smem
        {
            float e0 = __expf(sc[0][0]);
            float e1 = __expf(sc[0][1]);
            float e2 = __expf(sc[0][2]);
            float e3 = __expf(sc[0][3]);
            lsA0 += e0 + e1; lsB0 += e2 + e3;
            int j = chq * 8 + 2 * t4;
            *(u32*)&bPw[(q0 + grp) * 40 + j]     = cvt_bf16x2(e1, e0);
            *(u32*)&bPw[(q0 + 8 + grp) * 40 + j] = cvt_bf16x2(e3, e2);
            e0 = __expf(sc[1][0]);
            e1 = __expf(sc[1][1]);
            e2 = __expf(sc[1][2]);
            e3 = __expf(sc[1][3]);
            lsA1 += e0 + e1; lsB1 += e2 + e3;
            *(u32*)&bPw[(q0 + 16 + grp) * 40 + j] = cvt_bf16x2(e1, e0);
            *(u32*)&bPw[(q0 + 24 + grp) * 40 + j] = cvt_bf16x2(e3, e2);
        }

        // group barrier: 4 warps sharing qg exchange their P j-slices
        asm volatile("bar.sync %0, %1;" :: "r"(qg + 1), "r"(128) : "memory");

        // load P A-frags for both q-subtiles (rows q0..q0+31, all 32 j)
        u32 pa[2][2][4];
        #pragma unroll
        for (int qs = 0; qs < 2; qs++) {
            int row = q0 + qs * 16 + (l & 15);
            #pragma unroll
            for (int kj = 0; kj < 2; kj++)
                ldsm4(pa[qs][kj], s2u(&bPr[row * 40 + kj * 16 + ldA]));
        }

        // PV: V fragments loaded once, reused for BOTH q-subtiles
        #pragma unroll
        for (int g = 0; g < 4; g++) {
            int c0 = chq * 64 + g * 16 + ldA;
            #pragma unroll
            for (int kj = 0; kj < 2; kj++) {
                u32 vb4[4];
                ldsm4t(vb4, s2u(&bV[(kj * 16 + (l & 15)) * 264 + c0]));
                mma_bf16(acc[0][g * 2],     pa[0][kj], vb4[0], vb4[1]);
                mma_bf16(acc[0][g * 2 + 1], pa[0][kj], vb4[2], vb4[3]);
                mma_bf16(acc[1][g * 2],     pa[1][kj], vb4[0], vb4[1]);
                mma_bf16(acc[1][g * 2 + 1], pa[1][kj], vb4[2], vb4[3]);
            }
        }
        __syncthreads();   // all reads of buf done before it is overwritten
    }

    // lsum: quad reduce (lanes in a quad hold disjoint j columns of the slice)
    lsA0 += __shfl_xor_sync(0xffffffffu, lsA0, 1);
    lsA0 += __shfl_xor_sync(0xffffffffu, lsA0, 2);
    lsB0 += __shfl_xor_sync(0xffffffffu, lsB0, 1);
    lsB0 += __shfl_xor_sync(0xffffffffu, lsB0, 2);
    lsA1 += __shfl_xor_sync(0xffffffffu, lsA1, 1);
    lsA1 += __shfl_xor_sync(0xffffffffu, lsA1, 2);
    lsB1 += __shfl_xor_sync(0xffffffffu, lsB1, 1);
    lsB1 += __shfl_xor_sync(0xffffffffu, lsB1, 2);
    if (t4 == 0) {
        sL[chq * 128 + q0 + grp]      = lsA0;
        sL[chq * 128 + q0 + 8 + grp]  = lsB0;
        sL[chq * 128 + q0 + 16 + grp] = lsA1;
        sL[chq * 128 + q0 + 24 + grp] = lsB1;
    }
    __syncthreads();

    const float g = gmm[0];
    #pragma unroll
    for (int qs = 0; qs < 2; qs++) {
        int r0 = q0 + qs * 16 + grp;
        int r1 = r0 + 8;
        float L0 = sL[r0] + sL[128 + r0] + sL[256 + r0] + sL[384 + r0];
        float L1 = sL[r1] + sL[128 + r1] + sL[256 + r1] + sL[384 + r1];
        float rl0 = g / L0, rl1 = g / L1;
        int ir0 = i0 + r0;
        int ir1 = i0 + r1;
        #pragma unroll
        for (int t = 0; t < 8; t++) {
            int c0 = chq * 64 + t * 8 + 2 * t4;
            size_t base = ((size_t)b * CC + c0) * NN;
            outp[base + ir0]      = acc[qs][t][0] * rl0 + res[base + ir0];
            outp[base + NN + ir0] = acc[qs][t][1] * rl0 + res[base + NN + ir0];
            outp[base + ir1]      = acc[qs][t][2] * rl1 + res[base + ir1];
            outp[base + NN + ir1] = acc[qs][t][3] * rl1 + res[base + NN + ir1];
        }
    }
}

// ---------------------------------------------------------------------------

extern "C" void kernel_launch(void* const* d_in, const int* in_sizes, int n_in,
                              void* d_out, int out_size)
{
    const float* x   = (const float*)d_in[0];
    const float* y   = (const float*)d_in[1];
    const float* wqx = (const float*)d_in[2];
    const float* bqx = (const float*)d_in[3];
    const float* wkx = (const float*)d_in[4];
    const float* bkx = (const float*)d_in[5];
    const float* wvx = (const float*)d_in[6];
    const float* bvx = (const float*)d_in[7];
    const float* wqy = (const float*)d_in[8];
    const float* bqy = (const float*)d_in[9];
    const float* wky = (const float*)d_in[10];
    const float* bky = (const float*)d_in[11];
    const float* wvy = (const float*)d_in[12];
    const float* bvy = (const float*)d_in[13];
    const float* gx  = (const float*)d_in[14];
    const float* gy  = (const float*)d_in[15];
    float* out = (float*)d_out;

    cudaFuncSetAttribute(attn_kernel, cudaFuncAttributeMaxDynamicSharedMemorySize, ATTN_SMEM);

    dim3 pgrid(NN / 64, 320 / 64, 2 * BB);
    proj_tc_kernel<<<pgrid, 256>>>(x, y, wqx, bqx, wkx, bkx, wvx, bvx,
                                   wqy, bqy, wky, bky, wvy, bvy);

    dim3 agrid(NN / 128, BB, 2);
    attn_kernel<<<agrid, 512, ATTN_SMEM>>>(x, y, gx, gy, out);
}